// round 3
// baseline (speedup 1.0000x reference)
#include <cuda_runtime.h>
#include <cstdint>

// MessagePassing: out[row[e]] += x[col[e]]  for e in [0, E)
// x: [N, 32] f32; edge_index: [2, E] int32 (JAX silently downcasts int64
// without x64 enabled). row = ei[0:E], col = ei[E:2E].
// 8 threads per edge, each handling one float4 (16 B) of the 128 B message.
// Gather via LDG.128 (L2-resident x), scatter via red.global.add.v4.f32
// (no-return vectorized reduction -> 4x fewer L2 atomic ops, no round trip).

#define D 32

__global__ void mp_zero_kernel(float4* __restrict__ out, int n4) {
    int i = blockIdx.x * blockDim.x + threadIdx.x;
    if (i < n4) out[i] = make_float4(0.f, 0.f, 0.f, 0.f);
}

__global__ void mp_scatter_kernel(const float* __restrict__ x,
                                  const int* __restrict__ ei,
                                  float* __restrict__ out,
                                  int E, int N) {
    int tid = blockIdx.x * blockDim.x + threadIdx.x;
    int e = tid >> 3;           // edge id
    if (e >= E) return;
    int chunk = (tid & 7) << 2; // float offset within the 32-float row

    int row = ei[e];            // destination node
    int col = ei[E + e];        // source node
    if ((unsigned)row >= (unsigned)N || (unsigned)col >= (unsigned)N) return;

    const float4 v =
        *reinterpret_cast<const float4*>(x + (long long)col * D + chunk);
    float* dst = out + (long long)row * D + chunk;

    asm volatile("red.global.add.v4.f32 [%0], {%1, %2, %3, %4};"
                 :: "l"(dst), "f"(v.x), "f"(v.y), "f"(v.z), "f"(v.w)
                 : "memory");
}

extern "C" void kernel_launch(void* const* d_in, const int* in_sizes, int n_in,
                              void* d_out, int out_size) {
    const float* x = (const float*)d_in[0];
    const int* ei = (const int*)d_in[1];
    float* out = (float*)d_out;

    const int E = in_sizes[1] / 2;    // edge_index has 2*E elements
    const int N = in_sizes[0] / D;    // number of nodes
    const int n4 = out_size / 4;      // out: N*32 floats -> N*8 float4

    // 1) zero the output (harness poisons it with 0xAA)
    {
        int threads = 256;
        int blocks = (n4 + threads - 1) / threads;
        mp_zero_kernel<<<blocks, threads>>>((float4*)out, n4);
    }

    // 2) gather + vectorized scatter-add
    {
        long long total = (long long)E * 8;
        int threads = 256;
        int blocks = (int)((total + threads - 1) / threads);
        mp_scatter_kernel<<<blocks, threads>>>(x, ei, out, E, N);
    }
}

// round 4
// speedup vs baseline: 1.0921x; 1.0921x over previous
#include <cuda_runtime.h>
#include <cstdint>

// MessagePassing: out[row[e]] += x[col[e]]  for e in [0, E)
// x: [N, 32] f32; edge_index: [2, E] int32. row = ei[0:E], col = ei[E:2E].
//
// Latency-bound fix (R3 ncu: L2=49%, L1=59%, issue=20% -> nothing saturated):
// each thread owns one 16B chunk of U=4 consecutive edges. Indices come in as
// two int4 loads; the 4 gather LDG.128s are independent (MLP_p1=4), then 4
// red.global.add.v4.f32. Warp coalescing unchanged: at each sub-iteration,
// lanes 0-7 cover one edge's 128B row.

#define D 32
#define U 4

__global__ void mp_zero_kernel(float4* __restrict__ out, int n4) {
    int i = blockIdx.x * blockDim.x + threadIdx.x;
    if (i < n4) out[i] = make_float4(0.f, 0.f, 0.f, 0.f);
}

__device__ __forceinline__ void red_add_v4(float* dst, float4 v) {
    asm volatile("red.global.add.v4.f32 [%0], {%1, %2, %3, %4};"
                 :: "l"(dst), "f"(v.x), "f"(v.y), "f"(v.z), "f"(v.w)
                 : "memory");
}

__global__ void mp_scatter_kernel(const float* __restrict__ x,
                                  const int* __restrict__ ei,
                                  float* __restrict__ out,
                                  int E, int N) {
    int t = blockIdx.x * blockDim.x + threadIdx.x;
    int chunk = (t & 7) << 2;      // float offset within the 32-float row
    int g = t >> 3;                // edge-group id: edges [g*U, g*U+U)
    int e0 = g * U;
    if (e0 >= E) return;

    if (e0 + U <= E && (E & 3) == 0) {
        // fast path: vector index loads (16B-aligned since E % 4 == 0)
        int4 rows = *reinterpret_cast<const int4*>(ei + e0);
        int4 cols = *reinterpret_cast<const int4*>(ei + E + e0);

        int r[U] = {rows.x, rows.y, rows.z, rows.w};
        int c[U] = {cols.x, cols.y, cols.z, cols.w};

        float4 v[U];
        #pragma unroll
        for (int i = 0; i < U; i++) {
            int cc = ((unsigned)c[i] < (unsigned)N) ? c[i] : 0;
            v[i] = __ldg(reinterpret_cast<const float4*>(
                       x + (long long)cc * D + chunk));
        }
        #pragma unroll
        for (int i = 0; i < U; i++) {
            if ((unsigned)r[i] < (unsigned)N && (unsigned)c[i] < (unsigned)N)
                red_add_v4(out + (long long)r[i] * D + chunk, v[i]);
        }
    } else {
        // tail path: scalar index loads
        #pragma unroll
        for (int i = 0; i < U; i++) {
            int e = e0 + i;
            if (e >= E) break;
            int r = ei[e];
            int c = ei[E + e];
            if ((unsigned)r >= (unsigned)N || (unsigned)c >= (unsigned)N)
                continue;
            float4 v = __ldg(reinterpret_cast<const float4*>(
                           x + (long long)c * D + chunk));
            red_add_v4(out + (long long)r * D + chunk, v);
        }
    }
}

extern "C" void kernel_launch(void* const* d_in, const int* in_sizes, int n_in,
                              void* d_out, int out_size) {
    const float* x = (const float*)d_in[0];
    const int* ei = (const int*)d_in[1];
    float* out = (float*)d_out;

    const int E = in_sizes[1] / 2;    // edge_index has 2*E elements
    const int N = in_sizes[0] / D;    // number of nodes
    const int n4 = out_size / 4;      // out: N*32 floats -> N*8 float4

    // 1) zero the output (harness poisons it with 0xAA)
    {
        int threads = 256;
        int blocks = (n4 + threads - 1) / threads;
        mp_zero_kernel<<<blocks, threads>>>((float4*)out, n4);
    }

    // 2) gather + vectorized scatter-add, U edges per thread
    {
        long long groups = ((long long)E + U - 1) / U;
        long long total = groups * 8;
        int threads = 256;
        int blocks = (int)((total + threads - 1) / threads);
        mp_scatter_kernel<<<blocks, threads>>>(x, ei, out, E, N);
    }
}

// round 5
// speedup vs baseline: 1.0988x; 1.0062x over previous
#include <cuda_runtime.h>
#include <cstdint>

// MessagePassing: out[row[e]] += x[col[e]]  for e in [0, E)
// x: [N, 32] f32; edge_index: [2, E] int32. row = ei[0:E], col = ei[E:2E].
//
// R4 ncu: L2=66%, L1=80%, issue=19% — partially latency-bound. This round:
// U=8 edges per thread (8 independent gather LDG.128 in flight per thread),
// then 8 fire-and-forget red.global.add.v4.f32. Lanes 0-7 of each group
// cover one edge's 128B row per sub-iteration (1 L1tex wavefront/edge).

#define D 32
#define U 8

__global__ void mp_zero_kernel(float4* __restrict__ out, int n4) {
    int i = blockIdx.x * blockDim.x + threadIdx.x;
    if (i < n4) out[i] = make_float4(0.f, 0.f, 0.f, 0.f);
}

__device__ __forceinline__ void red_add_v4(float* dst, float4 v) {
    asm volatile("red.global.add.v4.f32 [%0], {%1, %2, %3, %4};"
                 :: "l"(dst), "f"(v.x), "f"(v.y), "f"(v.z), "f"(v.w)
                 : "memory");
}

__global__ __launch_bounds__(256) void mp_scatter_kernel(
        const float* __restrict__ x,
        const int* __restrict__ ei,
        float* __restrict__ out,
        int E, int N) {
    int t = blockIdx.x * blockDim.x + threadIdx.x;
    int chunk = (t & 7) << 2;      // float offset within the 32-float row
    int g = t >> 3;                // edge-group id: edges [g*U, g*U+U)
    int e0 = g * U;
    if (e0 >= E) return;

    if (e0 + U <= E && (E & 7) == 0) {
        // fast path: vector index loads (16B-aligned since E % 8 == 0)
        int4 r01 = *reinterpret_cast<const int4*>(ei + e0);
        int4 r23 = *reinterpret_cast<const int4*>(ei + e0 + 4);
        int4 c01 = *reinterpret_cast<const int4*>(ei + E + e0);
        int4 c23 = *reinterpret_cast<const int4*>(ei + E + e0 + 4);

        int r[U] = {r01.x, r01.y, r01.z, r01.w, r23.x, r23.y, r23.z, r23.w};
        int c[U] = {c01.x, c01.y, c01.z, c01.w, c23.x, c23.y, c23.z, c23.w};

        float4 v[U];
        #pragma unroll
        for (int i = 0; i < U; i++) {
            int cc = ((unsigned)c[i] < (unsigned)N) ? c[i] : 0;
            v[i] = __ldg(reinterpret_cast<const float4*>(
                       x + (long long)cc * D + chunk));
        }
        #pragma unroll
        for (int i = 0; i < U; i++) {
            if ((unsigned)r[i] < (unsigned)N && (unsigned)c[i] < (unsigned)N)
                red_add_v4(out + (long long)r[i] * D + chunk, v[i]);
        }
    } else {
        // tail path: scalar index loads
        #pragma unroll
        for (int i = 0; i < U; i++) {
            int e = e0 + i;
            if (e >= E) break;
            int r = ei[e];
            int c = ei[E + e];
            if ((unsigned)r >= (unsigned)N || (unsigned)c >= (unsigned)N)
                continue;
            float4 v = __ldg(reinterpret_cast<const float4*>(
                           x + (long long)c * D + chunk));
            red_add_v4(out + (long long)r * D + chunk, v);
        }
    }
}

extern "C" void kernel_launch(void* const* d_in, const int* in_sizes, int n_in,
                              void* d_out, int out_size) {
    const float* x = (const float*)d_in[0];
    const int* ei = (const int*)d_in[1];
    float* out = (float*)d_out;

    const int E = in_sizes[1] / 2;    // edge_index has 2*E elements
    const int N = in_sizes[0] / D;    // number of nodes
    const int n4 = out_size / 4;      // out: N*32 floats -> N*8 float4

    // 1) zero the output (harness poisons it with 0xAA)
    {
        int threads = 256;
        int blocks = (n4 + threads - 1) / threads;
        mp_zero_kernel<<<blocks, threads>>>((float4*)out, n4);
    }

    // 2) gather + vectorized scatter-add, U edges per thread
    {
        long long groups = ((long long)E + U - 1) / U;
        long long total = groups * 8;
        int threads = 256;
        int blocks = (int)((total + threads - 1) / threads);
        mp_scatter_kernel<<<blocks, threads>>>(x, ei, out, E, N);
    }
}